// round 11
// baseline (speedup 1.0000x reference)
#include <cuda_runtime.h>
#include <cuda_bf16.h>

#define SEQ    2048
#define BATCH  64
#define D      256
#define CHUNKS 8
#define CHUNK_S (SEQ / CHUNKS)   // 256
#define HSIZE  4096
#define HMASK  (HSIZE - 1)
#define NT     256

#define H1 100
#define H2 150
#define MT 1024                            // MLP threads per CTA

// smem float layout for mlp kernel
#define W1_STRIDE 257
#define W2_STRIDE 101
#define OFF_W1   0
#define OFF_W2   (OFF_W1 + H1 * W1_STRIDE)          // 25700
#define OFF_W3   (OFF_W2 + H2 * W2_STRIDE + 2)      // 40852
#define OFF_PL   (OFF_W3 + 300)                     // 41152
#define OFF_H1   (OFF_PL + D)                       // 41408
#define OFF_H2   (OFF_H1 + 104)                     // 41512
#define OFF_B1   (OFF_H2 + 152)                     // 41664
#define OFF_B2   (OFF_B1 + 104)                     // 41768
#define OFF_B3   (OFF_B2 + 152)                     // 41920
#define OFF_Z    (OFF_B3 + 4)                       // 41924
#define MLP_SMEM_FLOATS (OFF_Z + 8)
#define MLP_SMEM_BYTES  (MLP_SMEM_FLOATS * 4)       // ~167.7 KB

// Scratch (device globals — no allocations allowed)
__device__ float g_partial[BATCH * CHUNKS * D];
__device__ float g_warm[16];                        // L2-warming sink

__device__ __forceinline__ unsigned hash_tok(int tok) {
    return ((unsigned)tok * 2654435761u) & HMASK;
}

// ---------------------------------------------------------------------------
// Kernel 1: per (batch, seq-chunk) CTA — TF-IDF weighted embedding gather.
// Histogram packed into one uint32 per slot: (tok << 16) | count.
// vocab < 65536 and count <= 2048 both fit 16 bits. smem/CTA = 29 KB.
// 512 CTAs (~3.5/SM), ~28 warps/SM. CTAs 0-12 additionally stream the MLP
// weights via __ldcg to warm L2 for kernel 2.
// ---------------------------------------------------------------------------
__global__ __launch_bounds__(NT)
void pool_kernel(const int* __restrict__ x,
                 const float* __restrict__ emb,
                 const float* __restrict__ idf,
                 const float* __restrict__ W1, const float* __restrict__ b1,
                 const float* __restrict__ W2, const float* __restrict__ b2,
                 const float* __restrict__ W3, const float* __restrict__ b3) {
    __shared__ int      tok_sh[SEQ];      // 8 KB
    __shared__ unsigned htab[HSIZE];      // 16 KB packed (tok<<16)|cnt
    __shared__ float    w_sh[CHUNK_S];    // 1 KB
    __shared__ float4   red4[4][D / 4];   // 4 KB

    const int tid   = threadIdx.x;
    const int b     = blockIdx.x >> 3;    // batch
    const int chunk = blockIdx.x & 7;     // seq chunk

    #pragma unroll
    for (int i = tid; i < HSIZE; i += NT) htab[i] = 0u;
    #pragma unroll
    for (int s = tid; s < SEQ; s += NT) tok_sh[s] = x[s * BATCH + b];
    __syncthreads();

    // L2 warming for the MLP weights (blocks 0-12; deterministic sink write)
    if (blockIdx.x < 13) {
        float acc = 0.f;
        if (blockIdx.x < 8) {
            for (int i = blockIdx.x * NT + tid; i < H1 * D; i += 8 * NT)
                acc += __ldcg(W1 + i);
        } else if (blockIdx.x < 12) {
            for (int i = (blockIdx.x - 8) * NT + tid; i < H2 * H1; i += 4 * NT)
                acc += __ldcg(W2 + i);
        } else {
            if (tid < 300) acc += __ldcg(W3 + tid);
            if (tid < H1)  acc += __ldcg(b1 + tid);
            if (tid < H2)  acc += __ldcg(b2 + tid);
            if (tid < 2)   acc += __ldcg(b3 + tid);
        }
        if (tid == 0) g_warm[blockIdx.x] = acc;
    }

    // histogram insert: claim slot with CAS on (tok<<16), count in low 16
    #pragma unroll
    for (int s = tid; s < SEQ; s += NT) {
        int tok = tok_sh[s];
        if (tok == 0) continue;
        unsigned key = (unsigned)tok << 16;
        unsigned h = hash_tok(tok);
        while (true) {
            unsigned prev = atomicCAS(&htab[h], 0u, key);
            if (prev == 0u || (prev >> 16) == (unsigned)tok) {
                atomicAdd(&htab[h], 1u);
                break;
            }
            h = (h + 1) & HMASK;
        }
    }
    __syncthreads();

    const int base = chunk * CHUNK_S;
    {
        int i = tid;                       // CHUNK_S == NT
        int tok = tok_sh[base + i];
        float w = 0.0f;
        if (tok != 0) {
            unsigned h = hash_tok(tok);
            unsigned v;
            while (((v = htab[h]) >> 16) != (unsigned)tok) h = (h + 1) & HMASK;
            w = (float)(v & 0xffffu) * __ldg(&idf[tok]);
        }
        w_sh[i] = w;
    }
    __syncthreads();

    // gather: sg in [0,4) picks s ≡ sg (mod 4); dq in [0,64) picks float4 dim.
    // Two independent streams over [0,128) and [128,256).
    const int sg = tid >> 6;
    const int dq = tid & 63;
    const float4* emb4 = reinterpret_cast<const float4*>(emb);

    float4 acc0 = make_float4(0.f, 0.f, 0.f, 0.f);
    float4 acc1 = make_float4(0.f, 0.f, 0.f, 0.f);
    #pragma unroll 4
    for (int s = sg; s < CHUNK_S / 2; s += 4) {
        int   tokA = tok_sh[base + s];
        int   tokB = tok_sh[base + s + CHUNK_S / 2];
        float wA   = w_sh[s];
        float wB   = w_sh[s + CHUNK_S / 2];
        float4 vA  = __ldg(emb4 + (size_t)tokA * (D / 4) + dq);
        float4 vB  = __ldg(emb4 + (size_t)tokB * (D / 4) + dq);
        acc0.x += wA * vA.x;  acc0.y += wA * vA.y;
        acc0.z += wA * vA.z;  acc0.w += wA * vA.w;
        acc1.x += wB * vB.x;  acc1.y += wB * vB.y;
        acc1.z += wB * vB.z;  acc1.w += wB * vB.w;
    }
    acc0.x += acc1.x; acc0.y += acc1.y; acc0.z += acc1.z; acc0.w += acc1.w;
    red4[sg][dq] = acc0;
    __syncthreads();

    if (tid < D / 4) {
        float4 a = red4[0][tid];
        float4 c = red4[1][tid];
        float4 e = red4[2][tid];
        float4 f = red4[3][tid];
        float4 r = make_float4(a.x + c.x + e.x + f.x,
                               a.y + c.y + e.y + f.y,
                               a.z + c.z + e.z + f.z,
                               a.w + c.w + e.w + f.w);
        reinterpret_cast<float4*>(g_partial + ((size_t)b * CHUNKS + chunk) * D)[tid] = r;
    }
}

// ---------------------------------------------------------------------------
// Kernel 2: per-batch MLP, 64 CTAs x 1024 threads (unchanged from R10 except
// the 8-way partial reduce).
// ---------------------------------------------------------------------------
__global__ __launch_bounds__(MT, 1)
void mlp_kernel(const float* __restrict__ W1, const float* __restrict__ b1,
                const float* __restrict__ W2, const float* __restrict__ b2,
                const float* __restrict__ W3, const float* __restrict__ b3,
                float* __restrict__ out) {
    extern __shared__ float sm[];
    float* w1s = sm + OFF_W1;
    float* w2s = sm + OFF_W2;
    float* w3s = sm + OFF_W3;
    float* pls = sm + OFF_PL;
    float* h1s = sm + OFF_H1;
    float* h2s = sm + OFF_H2;
    float* b1s = sm + OFF_B1;
    float* b2s = sm + OFF_B2;
    float* b3s = sm + OFF_B3;
    float* zs  = sm + OFF_Z;

    const int tid = threadIdx.x;
    const int b   = blockIdx.x;

    // partial reduce -> pooled (threads 0-255), 8 chunks
    if (tid < D) {
        const float* p = g_partial + (size_t)b * CHUNKS * D;
        float s = 0.f;
        #pragma unroll
        for (int c = 0; c < CHUNKS; c++) s += __ldcg(p + c * D + tid);
        pls[tid] = s;
    }

    // stage W1 [100 x 256] -> stride 257
    const float4* W1v = reinterpret_cast<const float4*>(W1);
    for (int f = tid; f < H1 * (D / 4); f += MT) {
        int j  = f >> 6;
        int dq = f & 63;
        float4 v = __ldg(W1v + f);
        float* dst = w1s + j * W1_STRIDE + dq * 4;
        dst[0] = v.x; dst[1] = v.y; dst[2] = v.z; dst[3] = v.w;
    }
    // stage W2 [150 x 100] -> stride 101
    const float4* W2v = reinterpret_cast<const float4*>(W2);
    for (int f = tid; f < H2 * (H1 / 4); f += MT) {
        int j  = f / 25;
        int dq = f % 25;
        float4 v = __ldg(W2v + f);
        float* dst = w2s + j * W2_STRIDE + dq * 4;
        dst[0] = v.x; dst[1] = v.y; dst[2] = v.z; dst[3] = v.w;
    }
    // stage W3 + biases
    const float4* W3v = reinterpret_cast<const float4*>(W3);
    if (tid < 75) {
        float4 v = __ldg(W3v + tid);
        float* dst = w3s + tid * 4;
        dst[0] = v.x; dst[1] = v.y; dst[2] = v.z; dst[3] = v.w;
    }
    if (tid >= 128 && tid < 128 + H1) b1s[tid - 128] = __ldg(b1 + (tid - 128));
    if (tid >= 256 && tid < 256 + H2) b2s[tid - 256] = __ldg(b2 + (tid - 256));
    if (tid >= 448 && tid < 450)      b3s[tid - 448] = __ldg(b3 + (tid - 448));
    __syncthreads();

    // L1: quad per output; warp-aligned participation (tids [0,416))
    if (tid < 416) {
        const int j = tid >> 2;
        const int s = tid & 3;
        const float* w = w1s + j * W1_STRIDE;
        float a = 0.f;
        #pragma unroll 16
        for (int i = 0; i < D / 4; i++) {
            int d = 4 * i + s;
            a += pls[d] * w[d];
        }
        a += __shfl_xor_sync(0xffffffffu, a, 1);
        a += __shfl_xor_sync(0xffffffffu, a, 2);
        if (s == 0 && j < H1) h1s[j] = fmaxf(a + b1s[j], 0.f);
    }
    __syncthreads();

    // L2: quad per output; warp-aligned (tids [0,608))
    if (tid < 608) {
        const int j = tid >> 2;
        const int s = tid & 3;
        const float* w = w2s + j * W2_STRIDE;
        float a = 0.f;
        #pragma unroll
        for (int i = 0; i < H1 / 4; i++) {
            int d = 4 * i + s;
            a += h1s[d] * w[d];
        }
        a += __shfl_xor_sync(0xffffffffu, a, 1);
        a += __shfl_xor_sync(0xffffffffu, a, 2);
        if (s == 0 && j < H2) h2s[j] = fmaxf(a + b2s[j], 0.f);
    }
    __syncthreads();

    // L3: warp per logit (threads 0-63), shfl reduce.
    if (tid < 64) {
        const int o    = tid >> 5;
        const int lane = tid & 31;
        const float* w = w3s + o * H2;
        float a = 0.f;
        for (int d = lane; d < H2; d += 32) a += h2s[d] * w[d];
        #pragma unroll
        for (int off = 16; off; off >>= 1) a += __shfl_xor_sync(0xffffffffu, a, off);
        if (lane == 0) zs[o] = a + b3s[o];
    }
    __syncthreads();

    if (tid == 0) {
        float z0 = zs[0], z1 = zs[1];
        float m  = fmaxf(z0, z1);
        float e0 = expf(z0 - m);
        float e1 = expf(z1 - m);
        float inv = 1.0f / (e0 + e1);
        out[b * 2 + 0] = e0 * inv;
        out[b * 2 + 1] = e1 * inv;
    }
}

extern "C" void kernel_launch(void* const* d_in, const int* in_sizes, int n_in,
                              void* d_out, int out_size) {
    const int*   x   = (const int*)  d_in[0];
    const float* emb = (const float*)d_in[1];
    const float* idf = (const float*)d_in[2];
    const float* W1  = (const float*)d_in[3];
    const float* b1  = (const float*)d_in[4];
    const float* W2  = (const float*)d_in[5];
    const float* b2  = (const float*)d_in[6];
    const float* W3  = (const float*)d_in[7];
    const float* b3  = (const float*)d_in[8];
    float* out = (float*)d_out;

    static int smem_set = 0;
    if (!smem_set) {
        cudaFuncSetAttribute(mlp_kernel,
                             cudaFuncAttributeMaxDynamicSharedMemorySize,
                             MLP_SMEM_BYTES);
        smem_set = 1;
    }

    pool_kernel<<<BATCH * CHUNKS, NT>>>(x, emb, idf, W1, b1, W2, b2, W3, b3);
    mlp_kernel<<<BATCH, MT, MLP_SMEM_BYTES>>>(W1, b1, W2, b2, W3, b3, out);
}

// round 12
// speedup vs baseline: 1.2172x; 1.2172x over previous
#include <cuda_runtime.h>
#include <cuda_bf16.h>

#define SEQ    2048
#define BATCH  64
#define D      256
#define CHUNKS 4
#define CHUNK_S (SEQ / CHUNKS)   // 512
#define HSIZE  4096
#define HMASK  (HSIZE - 1)
#define NT     256

#define H1 100
#define H2 150
#define MT 1024                            // MLP threads per CTA

// smem float layout for mlp kernel
#define W1_STRIDE 257
#define W2_STRIDE 101
#define OFF_W1   0
#define OFF_W2   (OFF_W1 + H1 * W1_STRIDE)          // 25700
#define OFF_W3   (OFF_W2 + H2 * W2_STRIDE + 2)      // 40852
#define OFF_PL   (OFF_W3 + 300)                     // 41152
#define OFF_H1   (OFF_PL + D)                       // 41408
#define OFF_H2   (OFF_H1 + 104)                     // 41512
#define OFF_B1   (OFF_H2 + 152)                     // 41664
#define OFF_B2   (OFF_B1 + 104)                     // 41768
#define OFF_B3   (OFF_B2 + 152)                     // 41920
#define OFF_Z    (OFF_B3 + 4)                       // 41924
#define MLP_SMEM_FLOATS (OFF_Z + 8)
#define MLP_SMEM_BYTES  (MLP_SMEM_FLOATS * 4)       // ~167.7 KB

// Scratch (device globals — no allocations allowed)
__device__ float g_partial[BATCH * CHUNKS * D];

__device__ __forceinline__ unsigned hash_tok(int tok) {
    return ((unsigned)tok * 2654435761u) & HMASK;
}

// ---------------------------------------------------------------------------
// Kernel 1: per (batch, seq-chunk) CTA — TF-IDF weighted embedding gather.
// R10 structure (CHUNKS=4, 256 CTAs, no warming). Histogram packed into one
// uint32 per slot ((tok<<16)|cnt; vocab<65536, tf<=2048). Gather runs FOUR
// independent accumulator streams per thread to double outstanding LDG.128s
// on the latency-bound L2 reads.
// ---------------------------------------------------------------------------
__global__ __launch_bounds__(NT, 2)
void pool_kernel(const int* __restrict__ x,
                 const float* __restrict__ emb,
                 const float* __restrict__ idf) {
    __shared__ int      tok_sh[SEQ];      // 8 KB
    __shared__ unsigned htab[HSIZE];      // 16 KB packed (tok<<16)|cnt
    __shared__ float    w_sh[CHUNK_S];    // 2 KB
    __shared__ float4   red4[4][D / 4];   // 4 KB

    const int tid   = threadIdx.x;
    const int b     = blockIdx.x >> 2;    // batch
    const int chunk = blockIdx.x & 3;     // seq chunk

    #pragma unroll
    for (int i = tid; i < HSIZE; i += NT) htab[i] = 0u;
    #pragma unroll
    for (int s = tid; s < SEQ; s += NT) tok_sh[s] = x[s * BATCH + b];
    __syncthreads();

    // histogram insert: claim slot with CAS on (tok<<16), count in low 16
    #pragma unroll
    for (int s = tid; s < SEQ; s += NT) {
        int tok = tok_sh[s];
        if (tok == 0) continue;
        unsigned key = (unsigned)tok << 16;
        unsigned h = hash_tok(tok);
        while (true) {
            unsigned prev = atomicCAS(&htab[h], 0u, key);
            if (prev == 0u || (prev >> 16) == (unsigned)tok) {
                atomicAdd(&htab[h], 1u);
                break;
            }
            h = (h + 1) & HMASK;
        }
    }
    __syncthreads();

    const int base = chunk * CHUNK_S;
    for (int i = tid; i < CHUNK_S; i += NT) {
        int tok = tok_sh[base + i];
        float w = 0.0f;
        if (tok != 0) {
            unsigned h = hash_tok(tok);
            unsigned v;
            while (((v = htab[h]) >> 16) != (unsigned)tok) h = (h + 1) & HMASK;
            w = (float)(v & 0xffffu) * __ldg(&idf[tok]);
        }
        w_sh[i] = w;
    }
    __syncthreads();

    // gather: sg in [0,4) picks s ≡ sg (mod 4); dq in [0,64) picks float4 dim.
    // FOUR independent streams over seq quarters [0,128),[128,256),...
    const int sg = tid >> 6;
    const int dq = tid & 63;
    const float4* emb4 = reinterpret_cast<const float4*>(emb);

    float4 a0 = make_float4(0.f, 0.f, 0.f, 0.f);
    float4 a1 = make_float4(0.f, 0.f, 0.f, 0.f);
    float4 a2 = make_float4(0.f, 0.f, 0.f, 0.f);
    float4 a3 = make_float4(0.f, 0.f, 0.f, 0.f);
    const int Q = CHUNK_S / 4;            // 128
    #pragma unroll 2
    for (int i = 0; i < Q / 4; i++) {     // 32 iterations
        int s = sg + 4 * i;
        int  t0 = tok_sh[base + s];
        int  t1 = tok_sh[base + s + Q];
        int  t2 = tok_sh[base + s + 2 * Q];
        int  t3 = tok_sh[base + s + 3 * Q];
        float w0 = w_sh[s];
        float w1 = w_sh[s + Q];
        float w2 = w_sh[s + 2 * Q];
        float w3 = w_sh[s + 3 * Q];
        float4 v0 = __ldg(emb4 + (size_t)t0 * (D / 4) + dq);
        float4 v1 = __ldg(emb4 + (size_t)t1 * (D / 4) + dq);
        float4 v2 = __ldg(emb4 + (size_t)t2 * (D / 4) + dq);
        float4 v3 = __ldg(emb4 + (size_t)t3 * (D / 4) + dq);
        a0.x += w0 * v0.x;  a0.y += w0 * v0.y;  a0.z += w0 * v0.z;  a0.w += w0 * v0.w;
        a1.x += w1 * v1.x;  a1.y += w1 * v1.y;  a1.z += w1 * v1.z;  a1.w += w1 * v1.w;
        a2.x += w2 * v2.x;  a2.y += w2 * v2.y;  a2.z += w2 * v2.z;  a2.w += w2 * v2.w;
        a3.x += w3 * v3.x;  a3.y += w3 * v3.y;  a3.z += w3 * v3.z;  a3.w += w3 * v3.w;
    }
    a0.x += a1.x; a0.y += a1.y; a0.z += a1.z; a0.w += a1.w;
    a2.x += a3.x; a2.y += a3.y; a2.z += a3.z; a2.w += a3.w;
    a0.x += a2.x; a0.y += a2.y; a0.z += a2.z; a0.w += a2.w;
    red4[sg][dq] = a0;
    __syncthreads();

    if (tid < D / 4) {
        float4 a = red4[0][tid];
        float4 c = red4[1][tid];
        float4 e = red4[2][tid];
        float4 f = red4[3][tid];
        float4 r = make_float4(a.x + c.x + e.x + f.x,
                               a.y + c.y + e.y + f.y,
                               a.z + c.z + e.z + f.z,
                               a.w + c.w + e.w + f.w);
        reinterpret_cast<float4*>(g_partial + ((size_t)b * CHUNKS + chunk) * D)[tid] = r;
    }
}

// ---------------------------------------------------------------------------
// Kernel 2: per-batch MLP, 64 CTAs x 1024 threads (identical to R10 passing
// version).
// ---------------------------------------------------------------------------
__global__ __launch_bounds__(MT, 1)
void mlp_kernel(const float* __restrict__ W1, const float* __restrict__ b1,
                const float* __restrict__ W2, const float* __restrict__ b2,
                const float* __restrict__ W3, const float* __restrict__ b3,
                float* __restrict__ out) {
    extern __shared__ float sm[];
    float* w1s = sm + OFF_W1;
    float* w2s = sm + OFF_W2;
    float* w3s = sm + OFF_W3;
    float* pls = sm + OFF_PL;
    float* h1s = sm + OFF_H1;
    float* h2s = sm + OFF_H2;
    float* b1s = sm + OFF_B1;
    float* b2s = sm + OFF_B2;
    float* b3s = sm + OFF_B3;
    float* zs  = sm + OFF_Z;

    const int tid = threadIdx.x;
    const int b   = blockIdx.x;

    // partial reduce -> pooled (threads 0-255)
    if (tid < D) {
        const float* p = g_partial + (size_t)b * CHUNKS * D;
        float s = 0.f;
        #pragma unroll
        for (int c = 0; c < CHUNKS; c++) s += __ldcg(p + c * D + tid);
        pls[tid] = s;
    }

    // stage W1 [100 x 256] -> stride 257
    const float4* W1v = reinterpret_cast<const float4*>(W1);
    for (int f = tid; f < H1 * (D / 4); f += MT) {
        int j  = f >> 6;
        int dq = f & 63;
        float4 v = __ldg(W1v + f);
        float* dst = w1s + j * W1_STRIDE + dq * 4;
        dst[0] = v.x; dst[1] = v.y; dst[2] = v.z; dst[3] = v.w;
    }
    // stage W2 [150 x 100] -> stride 101
    const float4* W2v = reinterpret_cast<const float4*>(W2);
    for (int f = tid; f < H2 * (H1 / 4); f += MT) {
        int j  = f / 25;
        int dq = f % 25;
        float4 v = __ldg(W2v + f);
        float* dst = w2s + j * W2_STRIDE + dq * 4;
        dst[0] = v.x; dst[1] = v.y; dst[2] = v.z; dst[3] = v.w;
    }
    // stage W3 + biases
    const float4* W3v = reinterpret_cast<const float4*>(W3);
    if (tid < 75) {
        float4 v = __ldg(W3v + tid);
        float* dst = w3s + tid * 4;
        dst[0] = v.x; dst[1] = v.y; dst[2] = v.z; dst[3] = v.w;
    }
    if (tid >= 128 && tid < 128 + H1) b1s[tid - 128] = __ldg(b1 + (tid - 128));
    if (tid >= 256 && tid < 256 + H2) b2s[tid - 256] = __ldg(b2 + (tid - 256));
    if (tid >= 448 && tid < 450)      b3s[tid - 448] = __ldg(b3 + (tid - 448));
    __syncthreads();

    // L1: quad per output; warp-aligned participation (tids [0,416))
    if (tid < 416) {
        const int j = tid >> 2;
        const int s = tid & 3;
        const float* w = w1s + j * W1_STRIDE;
        float a = 0.f;
        #pragma unroll 16
        for (int i = 0; i < D / 4; i++) {
            int d = 4 * i + s;
            a += pls[d] * w[d];
        }
        a += __shfl_xor_sync(0xffffffffu, a, 1);
        a += __shfl_xor_sync(0xffffffffu, a, 2);
        if (s == 0 && j < H1) h1s[j] = fmaxf(a + b1s[j], 0.f);
    }
    __syncthreads();

    // L2: quad per output; warp-aligned (tids [0,608))
    if (tid < 608) {
        const int j = tid >> 2;
        const int s = tid & 3;
        const float* w = w2s + j * W2_STRIDE;
        float a = 0.f;
        #pragma unroll
        for (int i = 0; i < H1 / 4; i++) {
            int d = 4 * i + s;
            a += h1s[d] * w[d];
        }
        a += __shfl_xor_sync(0xffffffffu, a, 1);
        a += __shfl_xor_sync(0xffffffffu, a, 2);
        if (s == 0 && j < H2) h2s[j] = fmaxf(a + b2s[j], 0.f);
    }
    __syncthreads();

    // L3: warp per logit (threads 0-63), shfl reduce.
    if (tid < 64) {
        const int o    = tid >> 5;
        const int lane = tid & 31;
        const float* w = w3s + o * H2;
        float a = 0.f;
        for (int d = lane; d < H2; d += 32) a += h2s[d] * w[d];
        #pragma unroll
        for (int off = 16; off; off >>= 1) a += __shfl_xor_sync(0xffffffffu, a, off);
        if (lane == 0) zs[o] = a + b3s[o];
    }
    __syncthreads();

    if (tid == 0) {
        float z0 = zs[0], z1 = zs[1];
        float m  = fmaxf(z0, z1);
        float e0 = expf(z0 - m);
        float e1 = expf(z1 - m);
        float inv = 1.0f / (e0 + e1);
        out[b * 2 + 0] = e0 * inv;
        out[b * 2 + 1] = e1 * inv;
    }
}

extern "C" void kernel_launch(void* const* d_in, const int* in_sizes, int n_in,
                              void* d_out, int out_size) {
    const int*   x   = (const int*)  d_in[0];
    const float* emb = (const float*)d_in[1];
    const float* idf = (const float*)d_in[2];
    const float* W1  = (const float*)d_in[3];
    const float* b1  = (const float*)d_in[4];
    const float* W2  = (const float*)d_in[5];
    const float* b2  = (const float*)d_in[6];
    const float* W3  = (const float*)d_in[7];
    const float* b3  = (const float*)d_in[8];
    float* out = (float*)d_out;

    static int smem_set = 0;
    if (!smem_set) {
        cudaFuncSetAttribute(mlp_kernel,
                             cudaFuncAttributeMaxDynamicSharedMemorySize,
                             MLP_SMEM_BYTES);
        smem_set = 1;
    }

    pool_kernel<<<BATCH * CHUNKS, NT>>>(x, emb, idf);
    mlp_kernel<<<BATCH, MT, MLP_SMEM_BYTES>>>(W1, b1, W2, b2, W3, b3, out);
}

// round 13
// speedup vs baseline: 1.3109x; 1.0770x over previous
#include <cuda_runtime.h>
#include <cuda_bf16.h>

#define SEQ    2048
#define BATCH  64
#define D      256
#define CHUNKS 4
#define CHUNK_S (SEQ / CHUNKS)   // 512
#define HSIZE  4096
#define HMASK  (HSIZE - 1)
#define NT     256

#define H1 100
#define H2 150

// Scratch (device globals — no allocations allowed)
__device__ float g_partial[BATCH * CHUNKS * D];
__device__ int   g_count[BATCH];   // zero-init at load; self-resetting

__device__ __forceinline__ unsigned hash_tok(int tok) {
    return ((unsigned)tok * 2654435761u) & HMASK;
}

// ---------------------------------------------------------------------------
// Single fused kernel. 256 CTAs x 256 threads.
// Phase 1 (all CTAs): R12-proven pool — packed smem histogram + 4-stream
//   weighted embedding gather for this (batch, chunk); write partial.
// Phase 2 (last CTA per batch): MLP via quad-per-output with direct float4
//   weight reads (no smem staging) — each layer is ~1 parallel memory round.
// ---------------------------------------------------------------------------
__global__ __launch_bounds__(NT, 2)
void fused_kernel(const int*   __restrict__ x,
                  const float* __restrict__ emb,
                  const float* __restrict__ idf,
                  const float* __restrict__ W1, const float* __restrict__ b1,
                  const float* __restrict__ W2, const float* __restrict__ b2,
                  const float* __restrict__ W3, const float* __restrict__ b3,
                  float* __restrict__ out) {
    __shared__ int      tok_sh[SEQ];      // 8 KB
    __shared__ unsigned htab[HSIZE];      // 16 KB packed (tok<<16)|cnt
    __shared__ float    w_sh[CHUNK_S];    // 2 KB
    __shared__ float4   red4[4][D / 4];   // 4 KB
    // tail buffers
    __shared__ float4   pls4[D / 4];      // pooled, as float4
    __shared__ float4   h1s4[26];         // h1 (100 floats, padded to 104)
    __shared__ float    h2s[H2 + 2];
    __shared__ float    zs[2];
    __shared__ int      last_sh;

    const int tid   = threadIdx.x;
    const int b     = blockIdx.x >> 2;    // batch
    const int chunk = blockIdx.x & 3;     // seq chunk

    // ---------------- phase 1: pool ----------------
    #pragma unroll
    for (int i = tid; i < HSIZE; i += NT) htab[i] = 0u;
    #pragma unroll
    for (int s = tid; s < SEQ; s += NT) tok_sh[s] = x[s * BATCH + b];
    __syncthreads();

    #pragma unroll
    for (int s = tid; s < SEQ; s += NT) {
        int tok = tok_sh[s];
        if (tok == 0) continue;
        unsigned key = (unsigned)tok << 16;
        unsigned h = hash_tok(tok);
        while (true) {
            unsigned prev = atomicCAS(&htab[h], 0u, key);
            if (prev == 0u || (prev >> 16) == (unsigned)tok) {
                atomicAdd(&htab[h], 1u);
                break;
            }
            h = (h + 1) & HMASK;
        }
    }
    __syncthreads();

    const int base = chunk * CHUNK_S;
    for (int i = tid; i < CHUNK_S; i += NT) {
        int tok = tok_sh[base + i];
        float w = 0.0f;
        if (tok != 0) {
            unsigned h = hash_tok(tok);
            unsigned v;
            while (((v = htab[h]) >> 16) != (unsigned)tok) h = (h + 1) & HMASK;
            w = (float)(v & 0xffffu) * __ldg(&idf[tok]);
        }
        w_sh[i] = w;
    }
    __syncthreads();

    {
        const int sg = tid >> 6;
        const int dq = tid & 63;
        const float4* emb4 = reinterpret_cast<const float4*>(emb);

        float4 a0 = make_float4(0.f, 0.f, 0.f, 0.f);
        float4 a1 = make_float4(0.f, 0.f, 0.f, 0.f);
        float4 a2 = make_float4(0.f, 0.f, 0.f, 0.f);
        float4 a3 = make_float4(0.f, 0.f, 0.f, 0.f);
        const int Q = CHUNK_S / 4;            // 128
        #pragma unroll 2
        for (int i = 0; i < Q / 4; i++) {     // 32 iterations
            int s = sg + 4 * i;
            int  t0 = tok_sh[base + s];
            int  t1 = tok_sh[base + s + Q];
            int  t2 = tok_sh[base + s + 2 * Q];
            int  t3 = tok_sh[base + s + 3 * Q];
            float w0 = w_sh[s];
            float w1 = w_sh[s + Q];
            float w2 = w_sh[s + 2 * Q];
            float w3 = w_sh[s + 3 * Q];
            float4 v0 = __ldg(emb4 + (size_t)t0 * (D / 4) + dq);
            float4 v1 = __ldg(emb4 + (size_t)t1 * (D / 4) + dq);
            float4 v2 = __ldg(emb4 + (size_t)t2 * (D / 4) + dq);
            float4 v3 = __ldg(emb4 + (size_t)t3 * (D / 4) + dq);
            a0.x += w0 * v0.x;  a0.y += w0 * v0.y;  a0.z += w0 * v0.z;  a0.w += w0 * v0.w;
            a1.x += w1 * v1.x;  a1.y += w1 * v1.y;  a1.z += w1 * v1.z;  a1.w += w1 * v1.w;
            a2.x += w2 * v2.x;  a2.y += w2 * v2.y;  a2.z += w2 * v2.z;  a2.w += w2 * v2.w;
            a3.x += w3 * v3.x;  a3.y += w3 * v3.y;  a3.z += w3 * v3.z;  a3.w += w3 * v3.w;
        }
        a0.x += a1.x; a0.y += a1.y; a0.z += a1.z; a0.w += a1.w;
        a2.x += a3.x; a2.y += a3.y; a2.z += a3.z; a2.w += a3.w;
        a0.x += a2.x; a0.y += a2.y; a0.z += a2.z; a0.w += a2.w;
        red4[sg][dq] = a0;
        __syncthreads();

        if (tid < D / 4) {
            float4 a = red4[0][tid];
            float4 c = red4[1][tid];
            float4 e = red4[2][tid];
            float4 f = red4[3][tid];
            float4 r = make_float4(a.x + c.x + e.x + f.x,
                                   a.y + c.y + e.y + f.y,
                                   a.z + c.z + e.z + f.z,
                                   a.w + c.w + e.w + f.w);
            reinterpret_cast<float4*>(g_partial + ((size_t)b * CHUNKS + chunk) * D)[tid] = r;
        }
    }

    // ---------------- phase 2: last-CTA ticket ----------------
    __threadfence();
    __syncthreads();
    if (tid == 0) {
        int prev = atomicAdd(&g_count[b], 1);
        last_sh = (prev == CHUNKS - 1);
        if (last_sh) g_count[b] = 0;     // self-reset for graph replay
    }
    __syncthreads();
    if (!last_sh) return;

    // ---------------- phase 3: MLP tail (quad-per-output, no staging) ------
    // reduce partials -> pooled
    {
        const float* p = g_partial + (size_t)b * CHUNKS * D;
        float s = __ldcg(p + tid) + __ldcg(p + D + tid) +
                  __ldcg(p + 2 * D + tid) + __ldcg(p + 3 * D + tid);
        reinterpret_cast<float*>(pls4)[tid] = s;
    }
    __syncthreads();

    const int q = tid >> 2;      // quad id, 0..63
    const int s = tid & 3;       // quad lane

    // L1: j = q + 64*r, r in {0,1}. quad-thread s handles float4 idx s+4i.
    const float4* W1v = reinterpret_cast<const float4*>(W1);
    #pragma unroll
    for (int r = 0; r < 2; r++) {
        int j  = q + 64 * r;
        int jj = j < H1 ? j : H1 - 1;        // clamp to stay in-bounds
        const float4* w = W1v + (size_t)jj * (D / 4);
        float a = 0.f;
        #pragma unroll
        for (int i = 0; i < 16; i++) {
            float4 wv = __ldg(w + 4 * i + s);
            float4 pv = pls4[4 * i + s];
            a += wv.x * pv.x + wv.y * pv.y + wv.z * pv.z + wv.w * pv.w;
        }
        a += __shfl_xor_sync(0xffffffffu, a, 1);
        a += __shfl_xor_sync(0xffffffffu, a, 2);
        if (s == 0 && j < H1)
            reinterpret_cast<float*>(h1s4)[j] = fmaxf(a + __ldg(b1 + j), 0.f);
    }
    __syncthreads();

    // L2: j = q + 64*r, r in {0,1,2}. W2 row = 100 floats = 25 float4
    // (row byte offset 400 is 16B-aligned).
    #pragma unroll
    for (int r = 0; r < 3; r++) {
        int j  = q + 64 * r;
        int jj = j < H2 ? j : H2 - 1;
        const float4* w = reinterpret_cast<const float4*>(W2 + (size_t)jj * H1);
        float a = 0.f;
        #pragma unroll
        for (int idx = s; idx < 25; idx += 4) {
            float4 wv = __ldg(w + idx);
            float4 hv = h1s4[idx];
            a += wv.x * hv.x + wv.y * hv.y + wv.z * hv.z + wv.w * hv.w;
        }
        a += __shfl_xor_sync(0xffffffffu, a, 1);
        a += __shfl_xor_sync(0xffffffffu, a, 2);
        if (s == 0 && j < H2) h2s[j] = fmaxf(a + __ldg(b2 + j), 0.f);
    }
    __syncthreads();

    // L3: warp per logit (threads 0-63), shfl reduce.
    if (tid < 64) {
        const int o    = tid >> 5;
        const int lane = tid & 31;
        const float* w = W3 + (size_t)o * H2;
        float a = 0.f;
        #pragma unroll
        for (int d = lane; d < H2; d += 32) a += h2s[d] * __ldg(w + d);
        #pragma unroll
        for (int off = 16; off; off >>= 1) a += __shfl_xor_sync(0xffffffffu, a, off);
        if (lane == 0) zs[o] = a + __ldg(b3 + o);
    }
    __syncthreads();

    if (tid == 0) {
        float z0 = zs[0], z1 = zs[1];
        float m  = fmaxf(z0, z1);
        float e0 = expf(z0 - m);
        float e1 = expf(z1 - m);
        float inv = 1.0f / (e0 + e1);
        out[b * 2 + 0] = e0 * inv;
        out[b * 2 + 1] = e1 * inv;
    }
}

extern "C" void kernel_launch(void* const* d_in, const int* in_sizes, int n_in,
                              void* d_out, int out_size) {
    const int*   x   = (const int*)  d_in[0];
    const float* emb = (const float*)d_in[1];
    const float* idf = (const float*)d_in[2];
    const float* W1  = (const float*)d_in[3];
    const float* b1  = (const float*)d_in[4];
    const float* W2  = (const float*)d_in[5];
    const float* b2  = (const float*)d_in[6];
    const float* W3  = (const float*)d_in[7];
    const float* b3  = (const float*)d_in[8];
    float* out = (float*)d_out;

    fused_kernel<<<BATCH * CHUNKS, NT>>>(x, emb, idf,
                                         W1, b1, W2, b2, W3, b3, out);
}

// round 14
// speedup vs baseline: 1.4604x; 1.1140x over previous
#include <cuda_runtime.h>
#include <cuda_bf16.h>

#define SEQ    2048
#define BATCH  64
#define D      256
#define CHUNKS 4
#define CHUNK_S (SEQ / CHUNKS)   // 512
#define HSIZE  4096
#define HMASK  (HSIZE - 1)
#define NT     512               // threads per CTA

#define H1 100
#define H2 150

// Scratch (device globals — no allocations allowed)
__device__ float g_partial[BATCH * CHUNKS * D];
__device__ int   g_count[BATCH];   // zero-init at load; self-resetting

__device__ __forceinline__ unsigned hash_tok(int tok) {
    return ((unsigned)tok * 2654435761u) & HMASK;
}

// ---------------------------------------------------------------------------
// Single fused kernel. 256 CTAs x 512 threads (32 warps/SM at 2 CTAs/SM).
// Phase 1: packed smem histogram + weighted embedding gather (2 streams x 32
//          loads per thread), write partial pooled vector.
// Phase 2: last CTA per batch runs the MLP with quad-per-output direct
//          float4 weight reads (no smem staging).
// ---------------------------------------------------------------------------
__global__ __launch_bounds__(NT, 2)
void fused_kernel(const int*   __restrict__ x,
                  const float* __restrict__ emb,
                  const float* __restrict__ idf,
                  const float* __restrict__ W1, const float* __restrict__ b1,
                  const float* __restrict__ W2, const float* __restrict__ b2,
                  const float* __restrict__ W3, const float* __restrict__ b3,
                  float* __restrict__ out) {
    __shared__ int      tok_sh[SEQ];      // 8 KB
    __shared__ unsigned htab[HSIZE];      // 16 KB packed (tok<<16)|cnt
    __shared__ float    w_sh[CHUNK_S];    // 2 KB
    __shared__ float4   red4[8][D / 4];   // 8 KB
    // tail buffers
    __shared__ float4   pls4[D / 4];      // pooled (1 KB)
    __shared__ float4   h1s4[26];
    __shared__ float    h2s[H2 + 2];
    __shared__ float    zs[2];
    __shared__ int      last_sh;

    const int tid   = threadIdx.x;
    const int b     = blockIdx.x >> 2;    // batch
    const int chunk = blockIdx.x & 3;     // seq chunk

    // ---------------- phase 1: pool ----------------
    #pragma unroll
    for (int i = tid; i < HSIZE; i += NT) htab[i] = 0u;
    #pragma unroll
    for (int s = tid; s < SEQ; s += NT) tok_sh[s] = x[s * BATCH + b];
    __syncthreads();

    #pragma unroll
    for (int s = tid; s < SEQ; s += NT) {
        int tok = tok_sh[s];
        if (tok == 0) continue;
        unsigned key = (unsigned)tok << 16;
        unsigned h = hash_tok(tok);
        while (true) {
            unsigned prev = atomicCAS(&htab[h], 0u, key);
            if (prev == 0u || (prev >> 16) == (unsigned)tok) {
                atomicAdd(&htab[h], 1u);
                break;
            }
            h = (h + 1) & HMASK;
        }
    }
    __syncthreads();

    const int base = chunk * CHUNK_S;
    {
        int i = tid;                       // CHUNK_S == NT
        int tok = tok_sh[base + i];
        float w = 0.0f;
        if (tok != 0) {
            unsigned h = hash_tok(tok);
            unsigned v;
            while (((v = htab[h]) >> 16) != (unsigned)tok) h = (h + 1) & HMASK;
            w = (float)(v & 0xffffu) * __ldg(&idf[tok]);
        }
        w_sh[i] = w;
    }
    __syncthreads();

    {
        // gather: sg in [0,8) picks s ≡ sg (mod 8); dq in [0,64) = float4 dim.
        // Two independent streams over halves [0,256) and [256,512).
        const int sg = tid >> 6;
        const int dq = tid & 63;
        const float4* emb4 = reinterpret_cast<const float4*>(emb);

        float4 a0 = make_float4(0.f, 0.f, 0.f, 0.f);
        float4 a1 = make_float4(0.f, 0.f, 0.f, 0.f);
        const int HALF = CHUNK_S / 2;     // 256
        #pragma unroll 2
        for (int i = 0; i < HALF / 8; i++) {   // 32 iterations
            int s = sg + 8 * i;
            int   t0 = tok_sh[base + s];
            int   t1 = tok_sh[base + s + HALF];
            float w0 = w_sh[s];
            float w1 = w_sh[s + HALF];
            float4 v0 = __ldg(emb4 + (size_t)t0 * (D / 4) + dq);
            float4 v1 = __ldg(emb4 + (size_t)t1 * (D / 4) + dq);
            a0.x += w0 * v0.x;  a0.y += w0 * v0.y;
            a0.z += w0 * v0.z;  a0.w += w0 * v0.w;
            a1.x += w1 * v1.x;  a1.y += w1 * v1.y;
            a1.z += w1 * v1.z;  a1.w += w1 * v1.w;
        }
        a0.x += a1.x; a0.y += a1.y; a0.z += a1.z; a0.w += a1.w;
        red4[sg][dq] = a0;
        __syncthreads();

        if (tid < D / 4) {
            float4 r = red4[0][tid];
            #pragma unroll
            for (int k = 1; k < 8; k++) {
                float4 a = red4[k][tid];
                r.x += a.x; r.y += a.y; r.z += a.z; r.w += a.w;
            }
            reinterpret_cast<float4*>(g_partial + ((size_t)b * CHUNKS + chunk) * D)[tid] = r;
        }
    }

    // ---------------- phase 2: last-CTA ticket ----------------
    __threadfence();
    __syncthreads();
    if (tid == 0) {
        int prev = atomicAdd(&g_count[b], 1);
        last_sh = (prev == CHUNKS - 1);
        if (last_sh) g_count[b] = 0;     // self-reset for graph replay
    }
    __syncthreads();
    if (!last_sh) return;

    // ---------------- phase 3: MLP tail (quad-per-output, no staging) ------
    if (tid < D) {
        const float* p = g_partial + (size_t)b * CHUNKS * D;
        float s = __ldcg(p + tid) + __ldcg(p + D + tid) +
                  __ldcg(p + 2 * D + tid) + __ldcg(p + 3 * D + tid);
        reinterpret_cast<float*>(pls4)[tid] = s;
    }
    __syncthreads();

    const int q = tid >> 2;      // quad id, 0..127
    const int s = tid & 3;       // quad lane

    // L1: 100 outputs <= 128 quads -> one round.
    {
        int j  = q;
        int jj = j < H1 ? j : H1 - 1;
        const float4* w = reinterpret_cast<const float4*>(W1) + (size_t)jj * (D / 4);
        float a = 0.f;
        #pragma unroll
        for (int i = 0; i < 16; i++) {
            float4 wv = __ldg(w + 4 * i + s);
            float4 pv = pls4[4 * i + s];
            a += wv.x * pv.x + wv.y * pv.y + wv.z * pv.z + wv.w * pv.w;
        }
        a += __shfl_xor_sync(0xffffffffu, a, 1);
        a += __shfl_xor_sync(0xffffffffu, a, 2);
        if (s == 0 && j < H1)
            reinterpret_cast<float*>(h1s4)[j] = fmaxf(a + __ldg(b1 + j), 0.f);
    }
    __syncthreads();

    // L2: 150 outputs -> two rounds over 128 quads.
    #pragma unroll
    for (int r = 0; r < 2; r++) {
        int j  = q + 128 * r;
        int jj = j < H2 ? j : H2 - 1;
        const float4* w = reinterpret_cast<const float4*>(W2 + (size_t)jj * H1);
        float a = 0.f;
        #pragma unroll
        for (int idx = s; idx < 25; idx += 4) {
            float4 wv = __ldg(w + idx);
            float4 hv = h1s4[idx];
            a += wv.x * hv.x + wv.y * hv.y + wv.z * hv.z + wv.w * hv.w;
        }
        a += __shfl_xor_sync(0xffffffffu, a, 1);
        a += __shfl_xor_sync(0xffffffffu, a, 2);
        if (s == 0 && j < H2) h2s[j] = fmaxf(a + __ldg(b2 + j), 0.f);
    }
    __syncthreads();

    // L3: warp per logit (threads 0-63), shfl reduce.
    if (tid < 64) {
        const int o    = tid >> 5;
        const int lane = tid & 31;
        const float* w = W3 + (size_t)o * H2;
        float a = 0.f;
        #pragma unroll
        for (int d = lane; d < H2; d += 32) a += h2s[d] * __ldg(w + d);
        #pragma unroll
        for (int off = 16; off; off >>= 1) a += __shfl_xor_sync(0xffffffffu, a, off);
        if (lane == 0) zs[o] = a + __ldg(b3 + o);
    }
    __syncthreads();

    if (tid == 0) {
        float z0 = zs[0], z1 = zs[1];
        float m  = fmaxf(z0, z1);
        float e0 = expf(z0 - m);
        float e1 = expf(z1 - m);
        float inv = 1.0f / (e0 + e1);
        out[b * 2 + 0] = e0 * inv;
        out[b * 2 + 1] = e1 * inv;
    }
}

extern "C" void kernel_launch(void* const* d_in, const int* in_sizes, int n_in,
                              void* d_out, int out_size) {
    const int*   x   = (const int*)  d_in[0];
    const float* emb = (const float*)d_in[1];
    const float* idf = (const float*)d_in[2];
    const float* W1  = (const float*)d_in[3];
    const float* b1  = (const float*)d_in[4];
    const float* W2  = (const float*)d_in[5];
    const float* b2  = (const float*)d_in[6];
    const float* W3  = (const float*)d_in[7];
    const float* b3  = (const float*)d_in[8];
    float* out = (float*)d_out;

    fused_kernel<<<BATCH * CHUNKS, NT>>>(x, emb, idf,
                                         W1, b1, W2, b2, W3, b3, out);
}

// round 15
// speedup vs baseline: 1.4961x; 1.0245x over previous
#include <cuda_runtime.h>
#include <cuda_bf16.h>

#define SEQ    2048
#define BATCH  64
#define D      256
#define CHUNKS 4
#define CHUNK_S (SEQ / CHUNKS)   // 512
#define HSIZE  4096
#define HMASK  (HSIZE - 1)
#define NT     1024              // threads per CTA (64 warps/SM at 2 CTAs/SM)

#define H1 100
#define H2 150

// Scratch (device globals — no allocations allowed)
__device__ float g_partial[BATCH * CHUNKS * D];
__device__ int   g_count[BATCH];   // zero-init at load; self-resetting

__device__ __forceinline__ unsigned hash_tok(int tok) {
    return ((unsigned)tok * 2654435761u) & HMASK;
}

// ---------------------------------------------------------------------------
// Single fused kernel. 256 CTAs x 1024 threads = 2 CTAs/SM, 64 warps/SM.
// Phase 1: packed smem histogram + weighted embedding gather (one stream,
//          32 LDG.128 per thread), write partial pooled vector.
// Phase 2: last CTA per batch runs the MLP with quad-per-output direct
//          float4 weight reads (single round per layer at 256 quads).
// ---------------------------------------------------------------------------
__global__ __launch_bounds__(NT, 2)
void fused_kernel(const int*   __restrict__ x,
                  const float* __restrict__ emb,
                  const float* __restrict__ idf,
                  const float* __restrict__ W1, const float* __restrict__ b1,
                  const float* __restrict__ W2, const float* __restrict__ b2,
                  const float* __restrict__ W3, const float* __restrict__ b3,
                  float* __restrict__ out) {
    __shared__ int      tok_sh[SEQ];        // 8 KB
    __shared__ unsigned htab[HSIZE];        // 16 KB packed (tok<<16)|cnt
    __shared__ float    w_sh[CHUNK_S];      // 2 KB
    __shared__ float4   red4[16][D / 4];    // 16 KB
    // tail buffers
    __shared__ float4   pls4[D / 4];        // pooled (1 KB)
    __shared__ float4   h1s4[26];
    __shared__ float    h2s[H2 + 2];
    __shared__ float    zs[2];
    __shared__ int      last_sh;

    const int tid   = threadIdx.x;
    const int b     = blockIdx.x >> 2;      // batch
    const int chunk = blockIdx.x & 3;       // seq chunk

    // ---------------- phase 1: pool ----------------
    #pragma unroll
    for (int i = tid; i < HSIZE; i += NT) htab[i] = 0u;
    #pragma unroll
    for (int s = tid; s < SEQ; s += NT) tok_sh[s] = x[s * BATCH + b];
    __syncthreads();

    #pragma unroll
    for (int s = tid; s < SEQ; s += NT) {
        int tok = tok_sh[s];
        if (tok == 0) continue;
        unsigned key = (unsigned)tok << 16;
        unsigned h = hash_tok(tok);
        while (true) {
            unsigned prev = atomicCAS(&htab[h], 0u, key);
            if (prev == 0u || (prev >> 16) == (unsigned)tok) {
                atomicAdd(&htab[h], 1u);
                break;
            }
            h = (h + 1) & HMASK;
        }
    }
    __syncthreads();

    const int base = chunk * CHUNK_S;
    if (tid < CHUNK_S) {
        int tok = tok_sh[base + tid];
        float w = 0.0f;
        if (tok != 0) {
            unsigned h = hash_tok(tok);
            unsigned v;
            while (((v = htab[h]) >> 16) != (unsigned)tok) h = (h + 1) & HMASK;
            w = (float)(v & 0xffffu) * __ldg(&idf[tok]);
        }
        w_sh[tid] = w;
    }
    __syncthreads();

    {
        // gather: sg in [0,16) picks s ≡ sg (mod 16); dq in [0,64) float4 dim.
        // One accumulator stream, 32 iterations, unroll 4 (~4 loads in flight).
        const int sg = tid >> 6;
        const int dq = tid & 63;
        const float4* emb4 = reinterpret_cast<const float4*>(emb);

        float4 acc = make_float4(0.f, 0.f, 0.f, 0.f);
        #pragma unroll 4
        for (int s = sg; s < CHUNK_S; s += 16) {
            int   tok = tok_sh[base + s];
            float w   = w_sh[s];
            float4 v  = __ldg(emb4 + (size_t)tok * (D / 4) + dq);
            acc.x += w * v.x;
            acc.y += w * v.y;
            acc.z += w * v.z;
            acc.w += w * v.w;
        }
        red4[sg][dq] = acc;
        __syncthreads();

        if (tid < D / 4) {
            float4 r = red4[0][tid];
            #pragma unroll
            for (int k = 1; k < 16; k++) {
                float4 a = red4[k][tid];
                r.x += a.x; r.y += a.y; r.z += a.z; r.w += a.w;
            }
            reinterpret_cast<float4*>(g_partial + ((size_t)b * CHUNKS + chunk) * D)[tid] = r;
        }
    }

    // ---------------- phase 2: last-CTA ticket ----------------
    __threadfence();
    __syncthreads();
    if (tid == 0) {
        int prev = atomicAdd(&g_count[b], 1);
        last_sh = (prev == CHUNKS - 1);
        if (last_sh) g_count[b] = 0;       // self-reset for graph replay
    }
    __syncthreads();
    if (!last_sh) return;

    // ---------------- phase 3: MLP tail (quad-per-output, no staging) ------
    if (tid < D) {
        const float* p = g_partial + (size_t)b * CHUNKS * D;
        float s = __ldcg(p + tid) + __ldcg(p + D + tid) +
                  __ldcg(p + 2 * D + tid) + __ldcg(p + 3 * D + tid);
        reinterpret_cast<float*>(pls4)[tid] = s;
    }
    __syncthreads();

    const int q = tid >> 2;      // quad id, 0..255
    const int s = tid & 3;       // quad lane

    // L1: 100 outputs <= 256 quads -> one round.
    if (q < 128) {
        int j  = q;
        int jj = j < H1 ? j : H1 - 1;
        const float4* w = reinterpret_cast<const float4*>(W1) + (size_t)jj * (D / 4);
        float a = 0.f;
        #pragma unroll
        for (int i = 0; i < 16; i++) {
            float4 wv = __ldg(w + 4 * i + s);
            float4 pv = pls4[4 * i + s];
            a += wv.x * pv.x + wv.y * pv.y + wv.z * pv.z + wv.w * pv.w;
        }
        a += __shfl_xor_sync(0xffffffffu, a, 1);
        a += __shfl_xor_sync(0xffffffffu, a, 2);
        if (s == 0 && j < H1)
            reinterpret_cast<float*>(h1s4)[j] = fmaxf(a + __ldg(b1 + j), 0.f);
    }
    __syncthreads();

    // L2: 150 outputs <= 256 quads -> one round.
    {
        int j  = q;
        int jj = j < H2 ? j : H2 - 1;
        const float4* w = reinterpret_cast<const float4*>(W2 + (size_t)jj * H1);
        float a = 0.f;
        #pragma unroll
        for (int idx = s; idx < 25; idx += 4) {
            float4 wv = __ldg(w + idx);
            float4 hv = h1s4[idx];
            a += wv.x * hv.x + wv.y * hv.y + wv.z * hv.z + wv.w * hv.w;
        }
        a += __shfl_xor_sync(0xffffffffu, a, 1);
        a += __shfl_xor_sync(0xffffffffu, a, 2);
        if (s == 0 && j < H2) h2s[j] = fmaxf(a + __ldg(b2 + j), 0.f);
    }
    __syncthreads();

    // L3: warp per logit (threads 0-63), shfl reduce.
    if (tid < 64) {
        const int o    = tid >> 5;
        const int lane = tid & 31;
        const float* w = W3 + (size_t)o * H2;
        float a = 0.f;
        #pragma unroll
        for (int d = lane; d < H2; d += 32) a += h2s[d] * __ldg(w + d);
        #pragma unroll
        for (int off = 16; off; off >>= 1) a += __shfl_xor_sync(0xffffffffu, a, off);
        if (lane == 0) zs[o] = a + __ldg(b3 + o);
    }
    __syncthreads();

    if (tid == 0) {
        float z0 = zs[0], z1 = zs[1];
        float m  = fmaxf(z0, z1);
        float e0 = expf(z0 - m);
        float e1 = expf(z1 - m);
        float inv = 1.0f / (e0 + e1);
        out[b * 2 + 0] = e0 * inv;
        out[b * 2 + 1] = e1 * inv;
    }
}

extern "C" void kernel_launch(void* const* d_in, const int* in_sizes, int n_in,
                              void* d_out, int out_size) {
    const int*   x   = (const int*)  d_in[0];
    const float* emb = (const float*)d_in[1];
    const float* idf = (const float*)d_in[2];
    const float* W1  = (const float*)d_in[3];
    const float* b1  = (const float*)d_in[4];
    const float* W2  = (const float*)d_in[5];
    const float* b2  = (const float*)d_in[6];
    const float* W3  = (const float*)d_in[7];
    const float* b3  = (const float*)d_in[8];
    float* out = (float*)d_out;

    fused_kernel<<<BATCH * CHUNKS, NT>>>(x, emb, idf,
                                         W1, b1, W2, b2, W3, b3, out);
}